// round 6
// baseline (speedup 1.0000x reference)
#include <cuda_runtime.h>

// out[p, i*16+j] = x[p, i] * W[i, j] + b[i, j]
//   p in [0, P=B*T), i in [0,128), j in [0,16)
// x: [P, 128] f32, W: [128,16] f32, b: [128,16] f32, out: [P, 2048] f32
//
// v8 (256-bit) store variant for sm_103a:
//   - 256 eight-float chunks per position; thread t covers chunk (t&255) of
//     position p + (t>>8)  (512-thread block = 2 positions per iteration).
//   - Each thread holds its 8 weights + 8 biases in registers.
//   - One warp's st.global.cs.v8.f32 = 1024 contiguous bytes (32 full sectors).
//   - Streaming (.cs): output is write-once, never re-read.

#define C_IN   128
#define C_OUT  16
#define THREADS 512
#define POS_PER_ITER 2            // positions covered per block iteration
#define POS_PER_BLOCK 16
#define UNROLL 2                  // position-pair iterations unrolled

__device__ __forceinline__ void stg_cs_v8(float* p,
    float a0, float a1, float a2, float a3,
    float a4, float a5, float a6, float a7)
{
    asm volatile(
        "st.global.cs.v8.f32 [%0], {%1, %2, %3, %4, %5, %6, %7, %8};"
        :: "l"(p), "f"(a0), "f"(a1), "f"(a2), "f"(a3),
           "f"(a4), "f"(a5), "f"(a6), "f"(a7)
        : "memory");
}

__global__ __launch_bounds__(THREADS) void realembed_kernel(
    const float* __restrict__ x,
    const float* __restrict__ W,
    const float* __restrict__ bias,
    float* __restrict__ out,
    int P)
{
    const int t     = threadIdx.x;
    const int chunk = t & 255;           // v8-chunk within a position, 0..255
    const int pp    = t >> 8;            // 0 or 1: which position of the pair
    const int i     = chunk >> 1;        // feature 0..127
    const int h     = (chunk & 1) * 8;   // half of the 16 outputs

    // Preload this thread's 8 weights + 8 biases.
    const float4 wA = *reinterpret_cast<const float4*>(W    + i * C_OUT + h);
    const float4 wB = *reinterpret_cast<const float4*>(W    + i * C_OUT + h + 4);
    const float4 bA = *reinterpret_cast<const float4*>(bias + i * C_OUT + h);
    const float4 bB = *reinterpret_cast<const float4*>(bias + i * C_OUT + h + 4);

    int p0 = blockIdx.x * POS_PER_BLOCK;
    int p1 = p0 + POS_PER_BLOCK;
    if (p1 > P) p1 = P;

    int p = p0;
    // Main body: UNROLL pairs => UNROLL independent LDGs in flight, then stores.
    for (; p + UNROLL * POS_PER_ITER <= p1; p += UNROLL * POS_PER_ITER) {
        float xv[UNROLL];
        #pragma unroll
        for (int k = 0; k < UNROLL; ++k)
            xv[k] = __ldg(x + (size_t)(p + k * POS_PER_ITER + pp) * C_IN + i);

        #pragma unroll
        for (int k = 0; k < UNROLL; ++k) {
            const float v = xv[k];
            float* dst = out + (size_t)(p + k * POS_PER_ITER + pp) * (C_IN * C_OUT)
                             + chunk * 8;
            stg_cs_v8(dst,
                fmaf(v, wA.x, bA.x), fmaf(v, wA.y, bA.y),
                fmaf(v, wA.z, bA.z), fmaf(v, wA.w, bA.w),
                fmaf(v, wB.x, bB.x), fmaf(v, wB.y, bB.y),
                fmaf(v, wB.z, bB.z), fmaf(v, wB.w, bB.w));
        }
    }
    // Tail: handle remaining positions one pair-slot at a time.
    for (; p < p1; p += POS_PER_ITER) {
        const int pos = p + pp;
        if (pos < p1) {
            const float v = __ldg(x + (size_t)pos * C_IN + i);
            float* dst = out + (size_t)pos * (C_IN * C_OUT) + chunk * 8;
            stg_cs_v8(dst,
                fmaf(v, wA.x, bA.x), fmaf(v, wA.y, bA.y),
                fmaf(v, wA.z, bA.z), fmaf(v, wA.w, bA.w),
                fmaf(v, wB.x, bB.x), fmaf(v, wB.y, bB.y),
                fmaf(v, wB.z, bB.z), fmaf(v, wB.w, bB.w));
        }
    }
}

extern "C" void kernel_launch(void* const* d_in, const int* in_sizes, int n_in,
                              void* d_out, int out_size)
{
    const float* x  = (const float*)d_in[0];   // [P, 128]
    const float* W  = (const float*)d_in[1];   // [128, 16]
    const float* b  = (const float*)d_in[2];   // [128, 16]
    float* out = (float*)d_out;                // [P, 2048]

    const int P = in_sizes[0] / C_IN;          // B*T = 32768

    const int blocks = (P + POS_PER_BLOCK - 1) / POS_PER_BLOCK;
    realembed_kernel<<<blocks, THREADS>>>(x, W, b, out, P);
}

// round 7
// speedup vs baseline: 1.2473x; 1.2473x over previous
#include <cuda_runtime.h>

// out[p, i*16+j] = x[p, i] * W[i, j] + b[i, j]
//   p in [0, P=B*T), i in [0,128), j in [0,16)
// x: [P, 128] f32, W: [128,16] f32, b: [128,16] f32, out: [P, 2048] f32
//
// Chunk-per-thread (R5 structure): 512 threads; thread t owns float4 chunk t
// of each position (feature i = t>>2, quad q = t&3). Warp STG.128 = 512 B
// contiguous. Streaming stores (.cs): output is write-once.
//
// R7 change: all 8 positions' x loaded up front (MLP=8), then 8 store
// groups. __launch_bounds__(512, 4) pins regs at 32 so 4 CTAs/SM co-reside
// (32 regs x 2048 thr = 64K regs = full RF). R6 showed regs=40 costs a CTA.

#define C_IN   128
#define C_OUT  16
#define CHUNKS 512            // 2048 floats / 4 per position
#define POS_PER_BLOCK 8

__global__ __launch_bounds__(CHUNKS, 4) void realembed_kernel(
    const float* __restrict__ x,
    const float* __restrict__ W,
    const float* __restrict__ bias,
    float* __restrict__ out,
    int P)
{
    const int t = threadIdx.x;            // chunk index 0..511
    const int i = t >> 2;                 // feature 0..127
    const int q = t & 3;                  // quad within the 16 outputs

    const float4 w4 = *reinterpret_cast<const float4*>(W    + i * C_OUT + q * 4);
    const float4 b4 = *reinterpret_cast<const float4*>(bias + i * C_OUT + q * 4);

    const int p0 = blockIdx.x * POS_PER_BLOCK;

    const float* xp = x + (size_t)p0 * C_IN + i;
    float4*      op = reinterpret_cast<float4*>(out) + (size_t)p0 * CHUNKS + t;

    if (p0 + POS_PER_BLOCK <= P) {
        // Fast path: full tile. 8 independent LDGs in flight, then 8 stores.
        float xv[POS_PER_BLOCK];
        #pragma unroll
        for (int k = 0; k < POS_PER_BLOCK; ++k)
            xv[k] = __ldg(xp + k * C_IN);

        #pragma unroll
        for (int k = 0; k < POS_PER_BLOCK; ++k) {
            float4 o;
            o.x = fmaf(xv[k], w4.x, b4.x);
            o.y = fmaf(xv[k], w4.y, b4.y);
            o.z = fmaf(xv[k], w4.z, b4.z);
            o.w = fmaf(xv[k], w4.w, b4.w);
            __stcs(op + k * CHUNKS, o);
        }
    } else {
        // Tail (not hit for P=32768, kept for correctness).
        for (int k = 0; p0 + k < P && k < POS_PER_BLOCK; ++k) {
            float xv = __ldg(xp + k * C_IN);
            float4 o;
            o.x = fmaf(xv, w4.x, b4.x);
            o.y = fmaf(xv, w4.y, b4.y);
            o.z = fmaf(xv, w4.z, b4.z);
            o.w = fmaf(xv, w4.w, b4.w);
            __stcs(op + k * CHUNKS, o);
        }
    }
}

extern "C" void kernel_launch(void* const* d_in, const int* in_sizes, int n_in,
                              void* d_out, int out_size)
{
    const float* x  = (const float*)d_in[0];   // [P, 128]
    const float* W  = (const float*)d_in[1];   // [128, 16]
    const float* b  = (const float*)d_in[2];   // [128, 16]
    float* out = (float*)d_out;                // [P, 2048]

    const int P = in_sizes[0] / C_IN;          // B*T = 32768

    const int blocks = (P + POS_PER_BLOCK - 1) / POS_PER_BLOCK;
    realembed_kernel<<<blocks, CHUNKS>>>(x, W, b, out, P);
}